// round 1
// baseline (speedup 1.0000x reference)
#include <cuda_runtime.h>
#include <cuda_bf16.h>
#include <cstdint>

// Problem constants: I=16, O=8, J=4, B=16
//   n_in  = I*I*J = 1024
//   n_out = O*O*J = 256
//   K     = 1 + 2*O + O^2 = 81 projectors, but each output row r is hit by
//   exactly 4 of them (center, B(i,j), C(i), D(j)).
//
// out[b,r,c] = X[a0(r),a0(c)]
//            + (i_r==i_c)            * X[aC(r),aC(c)]
//            + (j_r==j_c)            * X[aD(r),aD(c)]
//            + (i_r==i_c && j_r==j_c)* X[aB(r),aB(c)]
// with r = (i*8+j)*4+ch and
//   a0 = ((2i+1)*16 + (2j+1))*4 + ch
//   aB = (32i + 2j)*4 + ch
//   aC = (32i + 2j + 1)*4 + ch
//   aD = ((2i+1)*16 + 2j)*4 + ch

#define N_IN   1024
#define N_OUT  256
#define BATCH  16

__global__ __launch_bounds__(256, 8)
void pool2d_density_kernel(const float* __restrict__ x, float* __restrict__ out)
{
    const int tid = threadIdx.x;
    const int g   = blockIdx.x;          // 0..1023 = b*64 + (i_r*8 + j_r)
    const int b    = g >> 6;
    const int ij_r = g & 63;
    const int i_r  = ij_r >> 3;
    const int j_r  = ij_r & 7;

    const int ch_r = tid >> 6;           // 0..3  (local output row)
    const int gc   = tid & 63;           // c-group: i_c*8 + j_c
    const int i_c  = gc >> 3;
    const int j_c  = gc & 7;

    const float* __restrict__ xb = x + (size_t)b * N_IN * N_IN;

    // X row indices for this output row
    const int A0r = ((2*i_r + 1)*16 + (2*j_r + 1))*4 + ch_r;
    const int ABr = (32*i_r + 2*j_r    )*4 + ch_r;
    const int ACr = (32*i_r + 2*j_r + 1)*4 + ch_r;
    const int ADr = ((2*i_r + 1)*16 + 2*j_r)*4 + ch_r;

    // X column bases (float index of ch_c=0; all multiples of 4 -> float4 ok)
    const int A0c = ((2*i_c + 1)*16 + (2*j_c + 1))*4;
    const int ABc = (32*i_c + 2*j_c    )*4;
    const int ACc = (32*i_c + 2*j_c + 1)*4;
    const int ADc = ((2*i_c + 1)*16 + 2*j_c)*4;

    // center term: always present
    float4 acc = *(const float4*)(xb + (size_t)A0r * N_IN + A0c);

    const bool im = (i_r == i_c);
    const bool jm = (j_r == j_c);

    if (im) {
        float4 v = *(const float4*)(xb + (size_t)ACr * N_IN + ACc);
        acc.x += v.x; acc.y += v.y; acc.z += v.z; acc.w += v.w;
    }
    if (jm) {
        float4 v = *(const float4*)(xb + (size_t)ADr * N_IN + ADc);
        acc.x += v.x; acc.y += v.y; acc.z += v.z; acc.w += v.w;
    }
    if (im && jm) {
        float4 v = *(const float4*)(xb + (size_t)ABr * N_IN + ABc);
        acc.x += v.x; acc.y += v.y; acc.z += v.z; acc.w += v.w;
    }

    const int r  = ij_r * 4 + ch_r;      // output row
    const int c0 = gc * 4;               // first of 4 output cols
    float4* o = (float4*)(out + (size_t)b * N_OUT * N_OUT + (size_t)r * N_OUT + c0);
    *o = acc;
}

extern "C" void kernel_launch(void* const* d_in, const int* in_sizes, int n_in,
                              void* d_out, int out_size)
{
    const float* x = (const float*)d_in[0];   // (16, 1024, 1024) fp32
    // d_in[1] (cols) and d_in[2] (mask) are deterministic from module constants
    // and are folded into the index formulas above.
    float* out = (float*)d_out;               // (16, 256, 256) fp32

    // 1024 blocks x 256 threads: each block = one (b, i_r, j_r) group (4 rows),
    // each thread = one float4 (4 contiguous ch_c outputs).
    pool2d_density_kernel<<<BATCH * 64, 256>>>(x, out);
}